// round 9
// baseline (speedup 1.0000x reference)
#include <cuda_runtime.h>
#include <cuda_bf16.h>
#include <cstdint>

// Problem constants
constexpr int B  = 4;
constexpr int S  = 2048;
constexpr int D  = 1024;
constexpr int H  = 16;
constexpr int DK = 64;
constexpr int M_TOTAL = B * S;   // 8192

constexpr int KA = 2 * D;        // 2048 (hi | lo)
constexpr size_t ACT_SLOT = (size_t)M_TOTAL * KA;
constexpr size_t W_SLOT   = (size_t)D * KA;
constexpr size_t HEAD_SLOT = (size_t)B * H * S * 128;

// ---------------------------------------------------------------------------
// Device scratch (allocation-free rule)
// ---------------------------------------------------------------------------
__device__ __nv_bfloat16 g_ab3[3 * ACT_SLOT];    // q,k,v acts; slot0 reused for attn out
__device__ __nv_bfloat16 g_wb4[4 * W_SLOT];      // w_q,w_k,w_v,w_o
__device__ __nv_bfloat16 g_qkvb[3 * HEAD_SLOT];  // Q,K,V head-major hi/lo

// ---------------------------------------------------------------------------
// helpers
// ---------------------------------------------------------------------------
__device__ __forceinline__ uint32_t smem_u32(const void* p) {
    uint32_t a;
    asm("{ .reg .u64 t; cvta.to.shared.u64 t, %1; cvt.u32.u64 %0, t; }"
        : "=r"(a) : "l"(p));
    return a;
}
__device__ __forceinline__ void cp16(uint32_t s, const void* g) {
    asm volatile("cp.async.cg.shared.global [%0], [%1], 16;" :: "r"(s), "l"(g));
}
__device__ __forceinline__ void ldmatrix_x4(uint32_t& r0, uint32_t& r1,
                                            uint32_t& r2, uint32_t& r3, uint32_t a) {
    asm volatile("ldmatrix.sync.aligned.m8n8.x4.shared.b16 {%0,%1,%2,%3}, [%4];"
                 : "=r"(r0), "=r"(r1), "=r"(r2), "=r"(r3) : "r"(a));
}
__device__ __forceinline__ void ldmatrix_x4_t(uint32_t& r0, uint32_t& r1,
                                              uint32_t& r2, uint32_t& r3, uint32_t a) {
    asm volatile("ldmatrix.sync.aligned.m8n8.x4.trans.shared.b16 {%0,%1,%2,%3}, [%4];"
                 : "=r"(r0), "=r"(r1), "=r"(r2), "=r"(r3) : "r"(a));
}
__device__ __forceinline__ void mma_bf16(float* c, const uint32_t* a, const uint32_t* b) {
    asm volatile("mma.sync.aligned.m16n8k16.row.col.f32.bf16.bf16.f32 "
                 "{%0,%1,%2,%3},{%4,%5,%6,%7},{%8,%9},{%0,%1,%2,%3};"
                 : "+f"(c[0]), "+f"(c[1]), "+f"(c[2]), "+f"(c[3])
                 : "r"(a[0]), "r"(a[1]), "r"(a[2]), "r"(a[3]), "r"(b[0]), "r"(b[1]));
}
__device__ __forceinline__ uint32_t cvt2bf(float phi, float plo) {
    uint32_t r;
    asm("cvt.rn.bf16x2.f32 %0, %1, %2;" : "=r"(r) : "f"(phi), "f"(plo));
    return r;
}
__device__ __forceinline__ float bf_lo(uint32_t p) { return __uint_as_float(p << 16); }
__device__ __forceinline__ float bf_hi(uint32_t p) { return __uint_as_float(p & 0xFFFF0000u); }

// ---------------------------------------------------------------------------
// Conversion kernels: fp32 [R, D] -> bf16 hi/lo [R, 2D]
// ---------------------------------------------------------------------------
__device__ __forceinline__ void conv_body(const float* __restrict__ X,
                                          __nv_bfloat16* __restrict__ Yb)
{
    const int i = (blockIdx.x * 256 + threadIdx.x) * 4;
    float4 x = *(const float4*)(X + i);
    const int row = i >> 10;
    const int col = i & (D - 1);
    float xv[4] = {x.x, x.y, x.z, x.w};
    uint32_t hp[2], lp[2];
#pragma unroll
    for (int j = 0; j < 2; j++) {
        hp[j] = cvt2bf(xv[2*j+1], xv[2*j]);
        lp[j] = cvt2bf(xv[2*j+1] - bf_hi(hp[j]), xv[2*j] - bf_lo(hp[j]));
    }
    uint32_t* ph = (uint32_t*)(Yb + (size_t)row * KA + col);
    uint32_t* pl = (uint32_t*)(Yb + (size_t)row * KA + D + col);
    ph[0] = hp[0]; ph[1] = hp[1];
    pl[0] = lp[0]; pl[1] = lp[1];
}

__global__ __launch_bounds__(256)
void conv_acts(const float* __restrict__ q, const float* __restrict__ k,
               const float* __restrict__ v, __nv_bfloat16* __restrict__ Y3)
{
    const int z = blockIdx.y;
    const float* X = (z == 0) ? q : (z == 1) ? k : v;
    conv_body(X, Y3 + (size_t)z * ACT_SLOT);
}

__global__ __launch_bounds__(256)
void conv_ws(const float* __restrict__ wq, const float* __restrict__ wk,
             const float* __restrict__ wv, const float* __restrict__ wo,
             __nv_bfloat16* __restrict__ Y4)
{
    const int z = blockIdx.y;
    const float* X = (z == 0) ? wq : (z == 1) ? wk : (z == 2) ? wv : wo;
    conv_body(X, Y4 + (size_t)z * W_SLOT);
}

// ---------------------------------------------------------------------------
// bf16 mma.sync GEMM, hi/lo split (3 products), 3-stage pipeline.
// Registers trimmed (A-frags loaded per-mi) to allow 2 CTAs/SM.
// Outer chunk loop forced rolled (#pragma unroll 1): keeps code small and
// avoids pathological ptxas scheduling under the register cap.
// ---------------------------------------------------------------------------
constexpr int BKC = 32;
constexpr int NCH = D / BKC;               // 32 chunks
constexpr int TILE_B  = 128 * BKC * 2;     // 8192 B
constexpr int STAGE_B = 4 * TILE_B;        // 32 KB
constexpr int GEMM_SMEM = 3 * STAGE_B;     // 96 KB

__global__ __launch_bounds__(256, 2)
void gemm_tc(const __nv_bfloat16* __restrict__ Ab, const __nv_bfloat16* __restrict__ Wb,
             const float* __restrict__ bq, const float* __restrict__ bk,
             const float* __restrict__ bv,
             float* __restrict__ Yf, __nv_bfloat16* __restrict__ Yb, int mode)
{
    extern __shared__ char smem[];
    const uint32_t sbase = smem_u32(smem);
    const int tid  = threadIdx.x;
    const int wid  = tid >> 5;
    const int lane = tid & 31;
    const int z = blockIdx.z;
    const int m0 = blockIdx.y * 128;
    const int n0 = blockIdx.x * 128;
    const int wm = (wid >> 2) * 64;
    const int wn = (wid & 3) * 32;

    Ab += (size_t)z * ACT_SLOT;
    Wb += (size_t)z * W_SLOT;
    const float* bias = (z == 0) ? bq : (z == 1) ? bk : bv;
    const float scale = (mode == 1 && z == 0) ? 0.125f : 1.0f;
    __nv_bfloat16* Ybz = Yb + (size_t)z * HEAD_SLOT;

    float acc[4][4][4];
#pragma unroll
    for (int mi = 0; mi < 4; mi++)
#pragma unroll
        for (int ni = 0; ni < 4; ni++)
#pragma unroll
            for (int r = 0; r < 4; r++) acc[mi][ni][r] = 0.f;

    const int lr = tid >> 1;
    const int lh = tid & 1;

    auto load_chunk = [&](int c) {
        const uint32_t stage = sbase + (uint32_t)(c % 3) * STAGE_B;
        const int kc = c * BKC;
        const int mg = lr >> 3, r8 = lr & 7;
        const __nv_bfloat16* ga = Ab + (size_t)(m0 + lr) * KA + kc;
        const __nv_bfloat16* gw = Wb + (size_t)(n0 + lr) * KA + kc;
#pragma unroll
        for (int j = 0; j < 2; j++) {
            const int kg = lh * 2 + j;
            const uint32_t so = (uint32_t)((kg * 16 + mg) * 128 + r8 * 16);
            cp16(stage + 0 * TILE_B + so, ga + kg * 8);
            cp16(stage + 1 * TILE_B + so, ga + D + kg * 8);
            cp16(stage + 2 * TILE_B + so, gw + kg * 8);
            cp16(stage + 3 * TILE_B + so, gw + D + kg * 8);
        }
        asm volatile("cp.async.commit_group;");
    };

    load_chunk(0);
    load_chunk(1);

    const int gA = lane >> 3;
    const int rA = lane & 7;

#pragma unroll 1
    for (int c = 0; c < NCH; c++) {
        if (c + 1 < NCH) asm volatile("cp.async.wait_group 1;" ::: "memory");
        else             asm volatile("cp.async.wait_group 0;" ::: "memory");
        __syncthreads();
        if (c + 2 < NCH) load_chunk(c + 2);

        const uint32_t stage = sbase + (uint32_t)(c % 3) * STAGE_B;
        const uint32_t ahiB = stage;
        const uint32_t aloB = stage + TILE_B;
        const uint32_t whiB = stage + 2 * TILE_B;
        const uint32_t wloB = stage + 3 * TILE_B;

#pragma unroll
        for (int ks = 0; ks < 2; ks++) {
            const int kg0 = ks * 2;
            uint32_t bhi[4][2], blo[4][2];
#pragma unroll
            for (int np = 0; np < 2; np++) {
                const int ng  = (wn >> 3) + 2 * np + (gA >> 1);
                const int kgB = kg0 + (gA & 1);
                const uint32_t off = (uint32_t)((kgB * 16 + ng) * 128 + rA * 16);
                ldmatrix_x4(bhi[2*np][0], bhi[2*np][1], bhi[2*np+1][0], bhi[2*np+1][1],
                            whiB + off);
                ldmatrix_x4(blo[2*np][0], blo[2*np][1], blo[2*np+1][0], blo[2*np+1][1],
                            wloB + off);
            }
#pragma unroll
            for (int mi = 0; mi < 4; mi++) {
                uint32_t ahi[4], alo[4];
                const int mgB = (wm >> 3) + mi * 2 + (gA & 1);
                const int kgB = kg0 + (gA >> 1);
                const uint32_t off = (uint32_t)((kgB * 16 + mgB) * 128 + rA * 16);
                ldmatrix_x4(ahi[0], ahi[1], ahi[2], ahi[3], ahiB + off);
                ldmatrix_x4(alo[0], alo[1], alo[2], alo[3], aloB + off);
#pragma unroll
                for (int ni = 0; ni < 4; ni++) {
                    mma_bf16(acc[mi][ni], ahi, bhi[ni]);
                    mma_bf16(acc[mi][ni], ahi, blo[ni]);
                    mma_bf16(acc[mi][ni], alo, bhi[ni]);
                }
            }
        }
    }

    // epilogue
#pragma unroll
    for (int mi = 0; mi < 4; mi++) {
#pragma unroll
        for (int ni = 0; ni < 4; ni++) {
            const int m = m0 + wm + mi * 16 + (lane >> 2);
            const int n = n0 + wn + ni * 8 + (lane & 3) * 2;
            const float b0 = __ldg(&bias[n]);
            const float b1 = __ldg(&bias[n + 1]);
            const float v00 = (acc[mi][ni][0] + b0) * scale;
            const float v01 = (acc[mi][ni][1] + b1) * scale;
            const float v10 = (acc[mi][ni][2] + b0) * scale;
            const float v11 = (acc[mi][ni][3] + b1) * scale;
            if (mode == 1) {
                const int h  = n >> 6;
                const int dk = n & (DK - 1);
#pragma unroll
                for (int rr = 0; rr < 2; rr++) {
                    const int mr = m + rr * 8;
                    const float p0 = rr ? v10 : v00;
                    const float p1 = rr ? v11 : v01;
                    const int bb = mr >> 11;
                    const int s  = mr & (S - 1);
                    __nv_bfloat16* base =
                        Ybz + (((size_t)bb * H + h) * S + s) * 128 + dk;
                    const uint32_t hp = cvt2bf(p1, p0);
                    const uint32_t lp = cvt2bf(p1 - bf_hi(hp), p0 - bf_lo(hp));
                    *(uint32_t*)(base)      = hp;
                    *(uint32_t*)(base + 64) = lp;
                }
            } else {
                *(float2*)(Yf + (size_t)m * D + n)       = make_float2(v00, v01);
                *(float2*)(Yf + (size_t)(m + 8) * D + n) = make_float2(v10, v11);
            }
        }
    }
}

// ---------------------------------------------------------------------------
// Tensor-core flash attention (bf16 hi/lo, 3 products each GEMM).
// kp-outer PV loop, 3-stage KV pipeline (stage 2 = recycled Q smem),
// outer tile loop forced rolled.
// ---------------------------------------------------------------------------
constexpr int ATQ = 128;
constexpr int ATK = 64;
constexpr int NKT = S / ATK;             // 32
constexpr int Q_SMEM = ATQ * 128 * 2;    // 32768
constexpr int K_SMEM = ATK * 128 * 2;    // 16384
constexpr int AT_STAGE = 2 * K_SMEM;     // 32768
constexpr int ATT_SMEM = Q_SMEM + 2 * AT_STAGE;  // 98304

__global__ __launch_bounds__(256, 2)
void attn_mma(const __nv_bfloat16* __restrict__ QKV, const int* __restrict__ mask,
              __nv_bfloat16* __restrict__ Aout)
{
    extern __shared__ char smem[];
    const uint32_t sq  = smem_u32(smem);
    const uint32_t skv = sq + Q_SMEM;
    const int tid = threadIdx.x, wid = tid >> 5, lane = tid & 31;
    const int b = blockIdx.z, h = blockIdx.y;
    const int q0blk = blockIdx.x * ATQ;
    const size_t headoff = ((size_t)(b * H + h) * S) * 128;
    const __nv_bfloat16* Qg = QKV + headoff + (size_t)q0blk * 128;
    const __nv_bfloat16* Kg = QKV + HEAD_SLOT + headoff;
    const __nv_bfloat16* Vg = QKV + 2 * HEAD_SLOT + headoff;
    const int wm = wid * 16;

    auto stage_of = [&](int c) -> uint32_t {
        const int s3 = c % 3;
        return (s3 == 0) ? skv : (s3 == 1) ? (skv + AT_STAGE) : sq;
    };

    auto load_kv = [&](int c) {
        const uint32_t st = stage_of(c);
        const int r = tid & 63, g = tid >> 6;
        const __nv_bfloat16* ks = Kg + (size_t)(c * ATK + r) * 128;
        const __nv_bfloat16* vs = Vg + (size_t)(c * ATK + r) * 128;
#pragma unroll
        for (int j = 0; j < 4; j++) {
            const int cg = g * 4 + j;
            const uint32_t so = (uint32_t)(((cg * 8 + (r >> 3)) * 8 + (r & 7)) * 16);
            cp16(st + so, ks + cg * 8);
            cp16(st + K_SMEM + so, vs + cg * 8);
        }
        asm volatile("cp.async.commit_group;");
    };

    // Q tile load (grouped with stage-0 commit)
    {
        const int r = tid & 127, half = tid >> 7;
        const __nv_bfloat16* src = Qg + (size_t)r * 128;
#pragma unroll
        for (int j = 0; j < 8; j++) {
            const int cg = half * 8 + j;
            const uint32_t so = (uint32_t)(((cg * 16 + (r >> 3)) * 8 + (r & 7)) * 16);
            cp16(sq + so, src + cg * 8);
        }
    }
    load_kv(0);
    load_kv(1);

    asm volatile("cp.async.wait_group 1;" ::: "memory");
    __syncthreads();

    const int gA = lane >> 3, rA = lane & 7;

    // Q fragments -> registers (sq becomes KV stage 2 afterwards)
    uint32_t qhi[4][4], qlo[4][4];
#pragma unroll
    for (int kk = 0; kk < 4; kk++) {
        const int rg = (wm >> 3) + (gA & 1);
        const int cgh = 2 * kk + (gA >> 1);
        ldmatrix_x4(qhi[kk][0], qhi[kk][1], qhi[kk][2], qhi[kk][3],
                    sq + (uint32_t)(((cgh * 16 + rg) * 8 + rA) * 16));
        ldmatrix_x4(qlo[kk][0], qlo[kk][1], qlo[kk][2], qlo[kk][3],
                    sq + (uint32_t)((((cgh + 8) * 16 + rg) * 8 + rA) * 16));
    }
    __syncthreads();

    float o[8][4];
#pragma unroll
    for (int ng = 0; ng < 8; ng++)
#pragma unroll
        for (int r = 0; r < 4; r++) o[ng][r] = 0.f;
    float m0 = -1e30f, m1 = -1e30f, l0 = 0.f, l1 = 0.f;

    const int r0l = lane >> 2, c0l = (lane & 3) * 2;
    const int qg0 = q0blk + wm + r0l;
    const int* mr0 = mask + ((size_t)b * S + qg0) * S + c0l;
    const int* mr1 = mr0 + 8 * S;

#pragma unroll 1
    for (int c = 0; c < NKT; c++) {
        if (c + 1 < NKT) asm volatile("cp.async.wait_group 1;" ::: "memory");
        else             asm volatile("cp.async.wait_group 0;" ::: "memory");
        __syncthreads();
        if (c + 2 < NKT) load_kv(c + 2);

        const uint32_t kb_ = stage_of(c);
        const uint32_t vb_ = kb_ + K_SMEM;

        // ---- scores ----
        float sc[8][4];
#pragma unroll
        for (int ng = 0; ng < 8; ng++)
#pragma unroll
            for (int r = 0; r < 4; r++) sc[ng][r] = 0.f;

#pragma unroll
        for (int ng = 0; ng < 8; ng += 2) {
#pragma unroll
            for (int kk = 0; kk < 4; kk++) {
                uint32_t kh[4], kl[4];
                const int rg = ng + (gA >> 1);
                const int cg = 2 * kk + (gA & 1);
                ldmatrix_x4(kh[0], kh[1], kh[2], kh[3],
                            kb_ + (uint32_t)(((cg * 8 + rg) * 8 + rA) * 16));
                ldmatrix_x4(kl[0], kl[1], kl[2], kl[3],
                            kb_ + (uint32_t)((((cg + 8) * 8 + rg) * 8 + rA) * 16));
                mma_bf16(sc[ng],     qhi[kk], kh + 0);
                mma_bf16(sc[ng],     qhi[kk], kl + 0);
                mma_bf16(sc[ng],     qlo[kk], kh + 0);
                mma_bf16(sc[ng + 1], qhi[kk], kh + 2);
                mma_bf16(sc[ng + 1], qhi[kk], kl + 2);
                mma_bf16(sc[ng + 1], qlo[kk], kh + 2);
            }
        }

        // ---- mask ----
        const int koff = c * ATK;
#pragma unroll
        for (int ng = 0; ng < 8; ng++) {
            const int2 mA = *(const int2*)(mr0 + koff + ng * 8);
            const int2 mB = *(const int2*)(mr1 + koff + ng * 8);
            if (mA.x == 0) sc[ng][0] = -1e9f;
            if (mA.y == 0) sc[ng][1] = -1e9f;
            if (mB.x == 0) sc[ng][2] = -1e9f;
            if (mB.y == 0) sc[ng][3] = -1e9f;
        }

        // ---- online softmax (max + rescale) ----
        float mx0 = sc[0][0], mx1 = sc[0][2];
#pragma unroll
        for (int ng = 0; ng < 8; ng++) {
            mx0 = fmaxf(mx0, fmaxf(sc[ng][0], sc[ng][1]));
            mx1 = fmaxf(mx1, fmaxf(sc[ng][2], sc[ng][3]));
        }
        mx0 = fmaxf(mx0, __shfl_xor_sync(0xffffffffu, mx0, 1));
        mx0 = fmaxf(mx0, __shfl_xor_sync(0xffffffffu, mx0, 2));
        mx1 = fmaxf(mx1, __shfl_xor_sync(0xffffffffu, mx1, 1));
        mx1 = fmaxf(mx1, __shfl_xor_sync(0xffffffffu, mx1, 2));

        const float mn0 = fmaxf(m0, mx0);
        const float mn1 = fmaxf(m1, mx1);
        const float cr0 = __expf(m0 - mn0);
        const float cr1 = __expf(m1 - mn1);
#pragma unroll
        for (int ng = 0; ng < 8; ng++) {
            o[ng][0] *= cr0; o[ng][1] *= cr0;
            o[ng][2] *= cr1; o[ng][3] *= cr1;
        }

        // ---- exp + P·V fused, kp-outer (phi/plo live range = 1 kp) ----
        float rs0 = 0.f, rs1 = 0.f;
#pragma unroll
        for (int kp = 0; kp < 4; kp++) {
            const float p00 = __expf(sc[2*kp][0]   - mn0);
            const float p01 = __expf(sc[2*kp][1]   - mn0);
            const float p10 = __expf(sc[2*kp][2]   - mn1);
            const float p11 = __expf(sc[2*kp][3]   - mn1);
            const float p20 = __expf(sc[2*kp+1][0] - mn0);
            const float p21 = __expf(sc[2*kp+1][1] - mn0);
            const float p30 = __expf(sc[2*kp+1][2] - mn1);
            const float p31 = __expf(sc[2*kp+1][3] - mn1);
            rs0 += (p00 + p01) + (p20 + p21);
            rs1 += (p10 + p11) + (p30 + p31);
            uint32_t phi[4], plo[4];
            phi[0] = cvt2bf(p01, p00);
            phi[1] = cvt2bf(p11, p10);
            phi[2] = cvt2bf(p21, p20);
            phi[3] = cvt2bf(p31, p30);
            plo[0] = cvt2bf(p01 - bf_hi(phi[0]), p00 - bf_lo(phi[0]));
            plo[1] = cvt2bf(p11 - bf_hi(phi[1]), p10 - bf_lo(phi[1]));
            plo[2] = cvt2bf(p21 - bf_hi(phi[2]), p20 - bf_lo(phi[2]));
            plo[3] = cvt2bf(p31 - bf_hi(phi[3]), p30 - bf_lo(phi[3]));

            const int rg = 2 * kp + (gA & 1);
#pragma unroll
            for (int ng = 0; ng < 8; ng += 2) {
                const int cg = ng + (gA >> 1);
                uint32_t vh[4], vl[4];
                ldmatrix_x4_t(vh[0], vh[1], vh[2], vh[3],
                              vb_ + (uint32_t)(((cg * 8 + rg) * 8 + rA) * 16));
                ldmatrix_x4_t(vl[0], vl[1], vl[2], vl[3],
                              vb_ + (uint32_t)((((cg + 8) * 8 + rg) * 8 + rA) * 16));
                mma_bf16(o[ng],     phi, vh + 0);
                mma_bf16(o[ng],     phi, vl + 0);
                mma_bf16(o[ng],     plo, vh + 0);
                mma_bf16(o[ng + 1], phi, vh + 2);
                mma_bf16(o[ng + 1], phi, vl + 2);
                mma_bf16(o[ng + 1], plo, vh + 2);
            }
        }
        l0 = l0 * cr0 + rs0 + __shfl_xor_sync(0xffffffffu, rs0, 1)
                            + __shfl_xor_sync(0xffffffffu, rs0, 2)
                            + __shfl_xor_sync(0xffffffffu, rs0, 3);
        l1 = l1 * cr1 + rs1 + __shfl_xor_sync(0xffffffffu, rs1, 1)
                            + __shfl_xor_sync(0xffffffffu, rs1, 2)
                            + __shfl_xor_sync(0xffffffffu, rs1, 3);
        m0 = mn0; m1 = mn1;
    }

    // ---- epilogue: bf16 hi/lo straight into the O-proj A buffer ----
    const float inv0 = 1.f / l0;
    const float inv1 = 1.f / l1;
    __nv_bfloat16* dst0 = Aout + (size_t)(b * S + qg0) * KA + h * DK + c0l;
    __nv_bfloat16* dst1 = dst0 + (size_t)8 * KA;
#pragma unroll
    for (int ng = 0; ng < 8; ng++) {
        const float x0 = o[ng][0] * inv0, x1 = o[ng][1] * inv0;
        const float y0 = o[ng][2] * inv1, y1 = o[ng][3] * inv1;
        const uint32_t hx = cvt2bf(x1, x0);
        const uint32_t lx = cvt2bf(x1 - bf_hi(hx), x0 - bf_lo(hx));
        const uint32_t hy = cvt2bf(y1, y0);
        const uint32_t ly = cvt2bf(y1 - bf_hi(hy), y0 - bf_lo(hy));
        *(uint32_t*)(dst0 + ng * 8)     = hx;
        *(uint32_t*)(dst0 + D + ng * 8) = lx;
        *(uint32_t*)(dst1 + ng * 8)     = hy;
        *(uint32_t*)(dst1 + D + ng * 8) = ly;
    }
}

// ---------------------------------------------------------------------------
// launch
// ---------------------------------------------------------------------------
extern "C" void kernel_launch(void* const* d_in, const int* in_sizes, int n_in,
                              void* d_out, int out_size)
{
    const float* query = (const float*)d_in[0];
    const float* key_  = (const float*)d_in[1];
    const float* value = (const float*)d_in[2];
    const int*   amask = (const int*)  d_in[3];
    const float* w_q = (const float*)d_in[4];
    const float* b_q = (const float*)d_in[5];
    const float* w_k = (const float*)d_in[6];
    const float* b_k = (const float*)d_in[7];
    const float* w_v = (const float*)d_in[8];
    const float* b_v = (const float*)d_in[9];
    const float* w_o = (const float*)d_in[10];
    const float* b_o = (const float*)d_in[11];
    float* out = (float*)d_out;

    __nv_bfloat16 *gab3, *gwb4, *gqkvb;
    cudaGetSymbolAddress((void**)&gab3,  g_ab3);
    cudaGetSymbolAddress((void**)&gwb4,  g_wb4);
    cudaGetSymbolAddress((void**)&gqkvb, g_qkvb);

    cudaFuncSetAttribute(gemm_tc, cudaFuncAttributeMaxDynamicSharedMemorySize, GEMM_SMEM);
    cudaFuncSetAttribute(attn_mma, cudaFuncAttributeMaxDynamicSharedMemorySize, ATT_SMEM);

    conv_acts<<<dim3(M_TOTAL * D / (4 * 256), 3), 256>>>(query, key_, value, gab3);
    conv_ws  <<<dim3(D * D / (4 * 256), 4), 256>>>(w_q, w_k, w_v, w_o, gwb4);

    gemm_tc<<<dim3(D / 128, M_TOTAL / 128, 3), 256, GEMM_SMEM>>>(
        gab3, gwb4, b_q, b_k, b_v, nullptr, gqkvb, 1);

    attn_mma<<<dim3(S / ATQ, H, B), 256, ATT_SMEM>>>(gqkvb, amask, gab3);

    gemm_tc<<<dim3(D / 128, M_TOTAL / 128, 1), 256, GEMM_SMEM>>>(
        gab3, gwb4 + 3 * W_SLOT, b_o, b_o, b_o, out, nullptr, 0);
}

// round 10
// speedup vs baseline: 1.3975x; 1.3975x over previous
#include <cuda_runtime.h>
#include <cuda_bf16.h>
#include <cstdint>

// Problem constants
constexpr int B  = 4;
constexpr int S  = 2048;
constexpr int D  = 1024;
constexpr int H  = 16;
constexpr int DK = 64;
constexpr int M_TOTAL = B * S;   // 8192

constexpr int KA = 2 * D;        // 2048 (hi | lo)
constexpr size_t ACT_SLOT = (size_t)M_TOTAL * KA;
constexpr size_t W_SLOT   = (size_t)D * KA;
constexpr size_t HEAD_SLOT = (size_t)B * H * S * 128;

// ---------------------------------------------------------------------------
// Device scratch (allocation-free rule)
// ---------------------------------------------------------------------------
__device__ __nv_bfloat16 g_ab3[3 * ACT_SLOT];    // q,k,v acts; slot0 reused for attn out
__device__ __nv_bfloat16 g_wb4[4 * W_SLOT];      // w_q,w_k,w_v,w_o
__device__ __nv_bfloat16 g_qkvb[3 * HEAD_SLOT];  // Q,K,V head-major hi/lo

// ---------------------------------------------------------------------------
// helpers
// ---------------------------------------------------------------------------
__device__ __forceinline__ uint32_t smem_u32(const void* p) {
    uint32_t a;
    asm("{ .reg .u64 t; cvta.to.shared.u64 t, %1; cvt.u32.u64 %0, t; }"
        : "=r"(a) : "l"(p));
    return a;
}
__device__ __forceinline__ void cp16(uint32_t s, const void* g) {
    asm volatile("cp.async.cg.shared.global [%0], [%1], 16;" :: "r"(s), "l"(g));
}
__device__ __forceinline__ void ldmatrix_x4(uint32_t& r0, uint32_t& r1,
                                            uint32_t& r2, uint32_t& r3, uint32_t a) {
    asm volatile("ldmatrix.sync.aligned.m8n8.x4.shared.b16 {%0,%1,%2,%3}, [%4];"
                 : "=r"(r0), "=r"(r1), "=r"(r2), "=r"(r3) : "r"(a));
}
__device__ __forceinline__ void ldmatrix_x4_t(uint32_t& r0, uint32_t& r1,
                                              uint32_t& r2, uint32_t& r3, uint32_t a) {
    asm volatile("ldmatrix.sync.aligned.m8n8.x4.trans.shared.b16 {%0,%1,%2,%3}, [%4];"
                 : "=r"(r0), "=r"(r1), "=r"(r2), "=r"(r3) : "r"(a));
}
__device__ __forceinline__ void mma_bf16(float* c, const uint32_t* a, const uint32_t* b) {
    asm volatile("mma.sync.aligned.m16n8k16.row.col.f32.bf16.bf16.f32 "
                 "{%0,%1,%2,%3},{%4,%5,%6,%7},{%8,%9},{%0,%1,%2,%3};"
                 : "+f"(c[0]), "+f"(c[1]), "+f"(c[2]), "+f"(c[3])
                 : "r"(a[0]), "r"(a[1]), "r"(a[2]), "r"(a[3]), "r"(b[0]), "r"(b[1]));
}
__device__ __forceinline__ uint32_t cvt2bf(float phi, float plo) {
    uint32_t r;
    asm("cvt.rn.bf16x2.f32 %0, %1, %2;" : "=r"(r) : "f"(phi), "f"(plo));
    return r;
}
__device__ __forceinline__ float bf_lo(uint32_t p) { return __uint_as_float(p << 16); }
__device__ __forceinline__ float bf_hi(uint32_t p) { return __uint_as_float(p & 0xFFFF0000u); }

// ---------------------------------------------------------------------------
// Conversion kernels: fp32 [R, D] -> bf16 hi/lo [R, 2D]
// ---------------------------------------------------------------------------
__device__ __forceinline__ void conv_body(const float* __restrict__ X,
                                          __nv_bfloat16* __restrict__ Yb)
{
    const int i = (blockIdx.x * 256 + threadIdx.x) * 4;
    float4 x = *(const float4*)(X + i);
    const int row = i >> 10;
    const int col = i & (D - 1);
    float xv[4] = {x.x, x.y, x.z, x.w};
    uint32_t hp[2], lp[2];
#pragma unroll
    for (int j = 0; j < 2; j++) {
        hp[j] = cvt2bf(xv[2*j+1], xv[2*j]);
        lp[j] = cvt2bf(xv[2*j+1] - bf_hi(hp[j]), xv[2*j] - bf_lo(hp[j]));
    }
    uint32_t* ph = (uint32_t*)(Yb + (size_t)row * KA + col);
    uint32_t* pl = (uint32_t*)(Yb + (size_t)row * KA + D + col);
    ph[0] = hp[0]; ph[1] = hp[1];
    pl[0] = lp[0]; pl[1] = lp[1];
}

__global__ __launch_bounds__(256)
void conv_acts(const float* __restrict__ q, const float* __restrict__ k,
               const float* __restrict__ v, __nv_bfloat16* __restrict__ Y3)
{
    const int z = blockIdx.y;
    const float* X = (z == 0) ? q : (z == 1) ? k : v;
    conv_body(X, Y3 + (size_t)z * ACT_SLOT);
}

__global__ __launch_bounds__(256)
void conv_ws(const float* __restrict__ wq, const float* __restrict__ wk,
             const float* __restrict__ wv, const float* __restrict__ wo,
             __nv_bfloat16* __restrict__ Y4)
{
    const int z = blockIdx.y;
    const float* X = (z == 0) ? wq : (z == 1) ? wk : (z == 2) ? wv : wo;
    conv_body(X, Y4 + (size_t)z * W_SLOT);
}

// ---------------------------------------------------------------------------
// bf16 mma.sync GEMM, hi/lo split (3 products), 3-stage pipeline.
// 512 threads / 16 warps, warp tile 32x32 -> acc = 32 regs/thread.
// 16 warps resident per SM by construction (no register cap needed).
// ---------------------------------------------------------------------------
constexpr int BKC = 32;
constexpr int NCH = D / BKC;               // 32 chunks
constexpr int TILE_B  = 128 * BKC * 2;     // 8192 B
constexpr int STAGE_B = 4 * TILE_B;        // 32 KB
constexpr int GEMM_SMEM = 3 * STAGE_B;     // 96 KB

__global__ __launch_bounds__(512)
void gemm_tc(const __nv_bfloat16* __restrict__ Ab, const __nv_bfloat16* __restrict__ Wb,
             const float* __restrict__ bq, const float* __restrict__ bk,
             const float* __restrict__ bv,
             float* __restrict__ Yf, __nv_bfloat16* __restrict__ Yb, int mode)
{
    extern __shared__ char smem[];
    const uint32_t sbase = smem_u32(smem);
    const int tid  = threadIdx.x;
    const int wid  = tid >> 5;
    const int lane = tid & 31;
    const int z = blockIdx.z;
    const int m0 = blockIdx.y * 128;
    const int n0 = blockIdx.x * 128;
    const int wm = (wid >> 2) * 32;        // 4 m-warps x 32 rows
    const int wn = (wid & 3) * 32;         // 4 n-warps x 32 cols

    Ab += (size_t)z * ACT_SLOT;
    Wb += (size_t)z * W_SLOT;
    const float* bias = (z == 0) ? bq : (z == 1) ? bk : bv;
    const float scale = (mode == 1 && z == 0) ? 0.125f : 1.0f;
    __nv_bfloat16* Ybz = Yb + (size_t)z * HEAD_SLOT;

    float acc[2][4][4];
#pragma unroll
    for (int mi = 0; mi < 2; mi++)
#pragma unroll
        for (int ni = 0; ni < 4; ni++)
#pragma unroll
            for (int r = 0; r < 4; r++) acc[mi][ni][r] = 0.f;

    // cooperative load: 512 threads, thread -> row tid>>2, quad tid&3
    const int lr = tid >> 2;
    const int lq = tid & 3;

    auto load_chunk = [&](int c) {
        const uint32_t stage = sbase + (uint32_t)(c % 3) * STAGE_B;
        const int kc = c * BKC;
        const int mg = lr >> 3, r8 = lr & 7;
        const __nv_bfloat16* ga = Ab + (size_t)(m0 + lr) * KA + kc;
        const __nv_bfloat16* gw = Wb + (size_t)(n0 + lr) * KA + kc;
        const uint32_t so = (uint32_t)((lq * 16 + mg) * 128 + r8 * 16);
        cp16(stage + 0 * TILE_B + so, ga + lq * 8);
        cp16(stage + 1 * TILE_B + so, ga + D + lq * 8);
        cp16(stage + 2 * TILE_B + so, gw + lq * 8);
        cp16(stage + 3 * TILE_B + so, gw + D + lq * 8);
        asm volatile("cp.async.commit_group;");
    };

    load_chunk(0);
    load_chunk(1);

    const int gA = lane >> 3;
    const int rA = lane & 7;

#pragma unroll 1
    for (int c = 0; c < NCH; c++) {
        if (c + 1 < NCH) asm volatile("cp.async.wait_group 1;" ::: "memory");
        else             asm volatile("cp.async.wait_group 0;" ::: "memory");
        __syncthreads();
        if (c + 2 < NCH) load_chunk(c + 2);

        const uint32_t stage = sbase + (uint32_t)(c % 3) * STAGE_B;
        const uint32_t ahiB = stage;
        const uint32_t aloB = stage + TILE_B;
        const uint32_t whiB = stage + 2 * TILE_B;
        const uint32_t wloB = stage + 3 * TILE_B;

#pragma unroll
        for (int ks = 0; ks < 2; ks++) {
            const int kg0 = ks * 2;
            uint32_t bhi[4][2], blo[4][2];
#pragma unroll
            for (int np = 0; np < 2; np++) {
                const int ng  = (wn >> 3) + 2 * np + (gA >> 1);
                const int kgB = kg0 + (gA & 1);
                const uint32_t off = (uint32_t)((kgB * 16 + ng) * 128 + rA * 16);
                ldmatrix_x4(bhi[2*np][0], bhi[2*np][1], bhi[2*np+1][0], bhi[2*np+1][1],
                            whiB + off);
                ldmatrix_x4(blo[2*np][0], blo[2*np][1], blo[2*np+1][0], blo[2*np+1][1],
                            wloB + off);
            }
#pragma unroll
            for (int mi = 0; mi < 2; mi++) {
                uint32_t ahi[4], alo[4];
                const int mgB = (wm >> 3) + mi * 2 + (gA & 1);
                const int kgB = kg0 + (gA >> 1);
                const uint32_t off = (uint32_t)((kgB * 16 + mgB) * 128 + rA * 16);
                ldmatrix_x4(ahi[0], ahi[1], ahi[2], ahi[3], ahiB + off);
                ldmatrix_x4(alo[0], alo[1], alo[2], alo[3], aloB + off);
#pragma unroll
                for (int ni = 0; ni < 4; ni++) {
                    mma_bf16(acc[mi][ni], ahi, bhi[ni]);
                    mma_bf16(acc[mi][ni], ahi, blo[ni]);
                    mma_bf16(acc[mi][ni], alo, bhi[ni]);
                }
            }
        }
    }

    // epilogue
#pragma unroll
    for (int mi = 0; mi < 2; mi++) {
#pragma unroll
        for (int ni = 0; ni < 4; ni++) {
            const int m = m0 + wm + mi * 16 + (lane >> 2);
            const int n = n0 + wn + ni * 8 + (lane & 3) * 2;
            const float b0 = __ldg(&bias[n]);
            const float b1 = __ldg(&bias[n + 1]);
            const float v00 = (acc[mi][ni][0] + b0) * scale;
            const float v01 = (acc[mi][ni][1] + b1) * scale;
            const float v10 = (acc[mi][ni][2] + b0) * scale;
            const float v11 = (acc[mi][ni][3] + b1) * scale;
            if (mode == 1) {
                const int h  = n >> 6;
                const int dk = n & (DK - 1);
#pragma unroll
                for (int rr = 0; rr < 2; rr++) {
                    const int mr = m + rr * 8;
                    const float p0 = rr ? v10 : v00;
                    const float p1 = rr ? v11 : v01;
                    const int bb = mr >> 11;
                    const int s  = mr & (S - 1);
                    __nv_bfloat16* base =
                        Ybz + (((size_t)bb * H + h) * S + s) * 128 + dk;
                    const uint32_t hp = cvt2bf(p1, p0);
                    const uint32_t lp = cvt2bf(p1 - bf_hi(hp), p0 - bf_lo(hp));
                    *(uint32_t*)(base)      = hp;
                    *(uint32_t*)(base + 64) = lp;
                }
            } else {
                *(float2*)(Yf + (size_t)m * D + n)       = make_float2(v00, v01);
                *(float2*)(Yf + (size_t)(m + 8) * D + n) = make_float2(v10, v11);
            }
        }
    }
}

// ---------------------------------------------------------------------------
// Tensor-core flash attention (bf16 hi/lo, 3 products each GEMM).
// ATK=32 key tiles -> sc[4][4] (16 regs): natural footprint fits 2 CTAs/SM
// without spills. 3-stage KV pipeline (stage 2 = recycled Q smem).
// ---------------------------------------------------------------------------
constexpr int ATQ = 128;
constexpr int ATK = 32;
constexpr int NKT = S / ATK;             // 64
constexpr int Q_SMEM = ATQ * 128 * 2;    // 32768
constexpr int KT_SMEM = ATK * 128 * 2;   // 8192 (K tile)
constexpr int AT_STAGE = 2 * KT_SMEM;    // 16384 (K + V)
constexpr int ATT_SMEM = Q_SMEM + 2 * AT_STAGE;  // 65536

__global__ __launch_bounds__(256, 2)
void attn_mma(const __nv_bfloat16* __restrict__ QKV, const int* __restrict__ mask,
              __nv_bfloat16* __restrict__ Aout)
{
    extern __shared__ char smem[];
    const uint32_t sq  = smem_u32(smem);
    const uint32_t skv = sq + Q_SMEM;
    const int tid = threadIdx.x, wid = tid >> 5, lane = tid & 31;
    const int b = blockIdx.z, h = blockIdx.y;
    const int q0blk = blockIdx.x * ATQ;
    const size_t headoff = ((size_t)(b * H + h) * S) * 128;
    const __nv_bfloat16* Qg = QKV + headoff + (size_t)q0blk * 128;
    const __nv_bfloat16* Kg = QKV + HEAD_SLOT + headoff;
    const __nv_bfloat16* Vg = QKV + 2 * HEAD_SLOT + headoff;
    const int wm = wid * 16;

    auto stage_of = [&](int c) -> uint32_t {
        const int s3 = c % 3;
        return (s3 == 0) ? skv : (s3 == 1) ? (skv + AT_STAGE) : sq;
    };

    auto load_kv = [&](int c) {
        const uint32_t st = stage_of(c);
        const int r = tid & 31, g = tid >> 5;   // 32 rows x 8 groups
        const __nv_bfloat16* ks = Kg + (size_t)(c * ATK + r) * 128;
        const __nv_bfloat16* vs = Vg + (size_t)(c * ATK + r) * 128;
#pragma unroll
        for (int j = 0; j < 2; j++) {
            const int cg = g * 2 + j;           // 16 col-groups (16B each)
            const uint32_t so = (uint32_t)(((cg * 4 + (r >> 3)) * 8 + (r & 7)) * 16);
            cp16(st + so, ks + cg * 8);
            cp16(st + KT_SMEM + so, vs + cg * 8);
        }
        asm volatile("cp.async.commit_group;");
    };

    // Q tile load (grouped with stage-0 commit)
    {
        const int r = tid & 127, half = tid >> 7;
        const __nv_bfloat16* src = Qg + (size_t)r * 128;
#pragma unroll
        for (int j = 0; j < 8; j++) {
            const int cg = half * 8 + j;
            const uint32_t so = (uint32_t)(((cg * 16 + (r >> 3)) * 8 + (r & 7)) * 16);
            cp16(sq + so, src + cg * 8);
        }
    }
    load_kv(0);
    load_kv(1);

    asm volatile("cp.async.wait_group 1;" ::: "memory");
    __syncthreads();

    const int gA = lane >> 3, rA = lane & 7;

    // Q fragments -> registers (sq becomes KV stage 2 afterwards)
    uint32_t qhi[4][4], qlo[4][4];
#pragma unroll
    for (int kk = 0; kk < 4; kk++) {
        const int rg = (wm >> 3) + (gA & 1);
        const int cgh = 2 * kk + (gA >> 1);
        ldmatrix_x4(qhi[kk][0], qhi[kk][1], qhi[kk][2], qhi[kk][3],
                    sq + (uint32_t)(((cgh * 16 + rg) * 8 + rA) * 16));
        ldmatrix_x4(qlo[kk][0], qlo[kk][1], qlo[kk][2], qlo[kk][3],
                    sq + (uint32_t)((((cgh + 8) * 16 + rg) * 8 + rA) * 16));
    }
    __syncthreads();

    float o[8][4];
#pragma unroll
    for (int ng = 0; ng < 8; ng++)
#pragma unroll
        for (int r = 0; r < 4; r++) o[ng][r] = 0.f;
    float m0 = -1e30f, m1 = -1e30f, l0 = 0.f, l1 = 0.f;

    const int r0l = lane >> 2, c0l = (lane & 3) * 2;
    const int qg0 = q0blk + wm + r0l;
    const int* mr0 = mask + ((size_t)b * S + qg0) * S + c0l;
    const int* mr1 = mr0 + 8 * S;

#pragma unroll 1
    for (int c = 0; c < NKT; c++) {
        if (c + 1 < NKT) asm volatile("cp.async.wait_group 1;" ::: "memory");
        else             asm volatile("cp.async.wait_group 0;" ::: "memory");
        __syncthreads();
        if (c + 2 < NKT) load_kv(c + 2);

        const uint32_t kb_ = stage_of(c);
        const uint32_t vb_ = kb_ + KT_SMEM;

        // ---- scores: 32 keys -> sc[4][4] ----
        float sc[4][4];
#pragma unroll
        for (int ng = 0; ng < 4; ng++)
#pragma unroll
            for (int r = 0; r < 4; r++) sc[ng][r] = 0.f;

#pragma unroll
        for (int ng = 0; ng < 4; ng += 2) {
#pragma unroll
            for (int kk = 0; kk < 4; kk++) {
                uint32_t kh[4], kl[4];
                const int rg = ng + (gA >> 1);          // 0..3 key row-groups
                const int cg = 2 * kk + (gA & 1);
                ldmatrix_x4(kh[0], kh[1], kh[2], kh[3],
                            kb_ + (uint32_t)(((cg * 4 + rg) * 8 + rA) * 16));
                ldmatrix_x4(kl[0], kl[1], kl[2], kl[3],
                            kb_ + (uint32_t)((((cg + 8) * 4 + rg) * 8 + rA) * 16));
                mma_bf16(sc[ng],     qhi[kk], kh + 0);
                mma_bf16(sc[ng],     qhi[kk], kl + 0);
                mma_bf16(sc[ng],     qlo[kk], kh + 0);
                mma_bf16(sc[ng + 1], qhi[kk], kh + 2);
                mma_bf16(sc[ng + 1], qhi[kk], kl + 2);
                mma_bf16(sc[ng + 1], qlo[kk], kh + 2);
            }
        }

        // ---- mask ----
        const int koff = c * ATK;
#pragma unroll
        for (int ng = 0; ng < 4; ng++) {
            const int2 mA = *(const int2*)(mr0 + koff + ng * 8);
            const int2 mB = *(const int2*)(mr1 + koff + ng * 8);
            if (mA.x == 0) sc[ng][0] = -1e9f;
            if (mA.y == 0) sc[ng][1] = -1e9f;
            if (mB.x == 0) sc[ng][2] = -1e9f;
            if (mB.y == 0) sc[ng][3] = -1e9f;
        }

        // ---- online softmax ----
        float mx0 = sc[0][0], mx1 = sc[0][2];
#pragma unroll
        for (int ng = 0; ng < 4; ng++) {
            mx0 = fmaxf(mx0, fmaxf(sc[ng][0], sc[ng][1]));
            mx1 = fmaxf(mx1, fmaxf(sc[ng][2], sc[ng][3]));
        }
        mx0 = fmaxf(mx0, __shfl_xor_sync(0xffffffffu, mx0, 1));
        mx0 = fmaxf(mx0, __shfl_xor_sync(0xffffffffu, mx0, 2));
        mx1 = fmaxf(mx1, __shfl_xor_sync(0xffffffffu, mx1, 1));
        mx1 = fmaxf(mx1, __shfl_xor_sync(0xffffffffu, mx1, 2));

        const float mn0 = fmaxf(m0, mx0);
        const float mn1 = fmaxf(m1, mx1);
        const float cr0 = __expf(m0 - mn0);
        const float cr1 = __expf(m1 - mn1);
#pragma unroll
        for (int ng = 0; ng < 8; ng++) {
            o[ng][0] *= cr0; o[ng][1] *= cr0;
            o[ng][2] *= cr1; o[ng][3] *= cr1;
        }

        // ---- exp + P·V fused, kp-outer (2 kp of 16 keys) ----
        float rs0 = 0.f, rs1 = 0.f;
#pragma unroll
        for (int kp = 0; kp < 2; kp++) {
            const float p00 = __expf(sc[2*kp][0]   - mn0);
            const float p01 = __expf(sc[2*kp][1]   - mn0);
            const float p10 = __expf(sc[2*kp][2]   - mn1);
            const float p11 = __expf(sc[2*kp][3]   - mn1);
            const float p20 = __expf(sc[2*kp+1][0] - mn0);
            const float p21 = __expf(sc[2*kp+1][1] - mn0);
            const float p30 = __expf(sc[2*kp+1][2] - mn1);
            const float p31 = __expf(sc[2*kp+1][3] - mn1);
            rs0 += (p00 + p01) + (p20 + p21);
            rs1 += (p10 + p11) + (p30 + p31);
            uint32_t phi[4], plo[4];
            phi[0] = cvt2bf(p01, p00);
            phi[1] = cvt2bf(p11, p10);
            phi[2] = cvt2bf(p21, p20);
            phi[3] = cvt2bf(p31, p30);
            plo[0] = cvt2bf(p01 - bf_hi(phi[0]), p00 - bf_lo(phi[0]));
            plo[1] = cvt2bf(p11 - bf_hi(phi[1]), p10 - bf_lo(phi[1]));
            plo[2] = cvt2bf(p21 - bf_hi(phi[2]), p20 - bf_lo(phi[2]));
            plo[3] = cvt2bf(p31 - bf_hi(phi[3]), p30 - bf_lo(phi[3]));

            const int rg = 2 * kp + (gA & 1);   // 0..3 key row-groups
#pragma unroll
            for (int ng = 0; ng < 8; ng += 2) {
                const int cg = ng + (gA >> 1);  // dk col-groups 0..7 (hi)
                uint32_t vh[4], vl[4];
                ldmatrix_x4_t(vh[0], vh[1], vh[2], vh[3],
                              vb_ + (uint32_t)(((cg * 4 + rg) * 8 + rA) * 16));
                ldmatrix_x4_t(vl[0], vl[1], vl[2], vl[3],
                              vb_ + (uint32_t)((((cg + 8) * 4 + rg) * 8 + rA) * 16));
                mma_bf16(o[ng],     phi, vh + 0);
                mma_bf16(o[ng],     phi, vl + 0);
                mma_bf16(o[ng],     plo, vh + 0);
                mma_bf16(o[ng + 1], phi, vh + 2);
                mma_bf16(o[ng + 1], phi, vl + 2);
                mma_bf16(o[ng + 1], plo, vh + 2);
            }
        }
        rs0 += __shfl_xor_sync(0xffffffffu, rs0, 1);
        rs0 += __shfl_xor_sync(0xffffffffu, rs0, 2);
        rs1 += __shfl_xor_sync(0xffffffffu, rs1, 1);
        rs1 += __shfl_xor_sync(0xffffffffu, rs1, 2);
        l0 = l0 * cr0 + rs0;
        l1 = l1 * cr1 + rs1;
        m0 = mn0; m1 = mn1;
    }

    // ---- epilogue: bf16 hi/lo straight into the O-proj A buffer ----
    const float inv0 = 1.f / l0;
    const float inv1 = 1.f / l1;
    __nv_bfloat16* dst0 = Aout + (size_t)(b * S + qg0) * KA + h * DK + c0l;
    __nv_bfloat16* dst1 = dst0 + (size_t)8 * KA;
#pragma unroll
    for (int ng = 0; ng < 8; ng++) {
        const float x0 = o[ng][0] * inv0, x1 = o[ng][1] * inv0;
        const float y0 = o[ng][2] * inv1, y1 = o[ng][3] * inv1;
        const uint32_t hx = cvt2bf(x1, x0);
        const uint32_t lx = cvt2bf(x1 - bf_hi(hx), x0 - bf_lo(hx));
        const uint32_t hy = cvt2bf(y1, y0);
        const uint32_t ly = cvt2bf(y1 - bf_hi(hy), y0 - bf_lo(hy));
        *(uint32_t*)(dst0 + ng * 8)     = hx;
        *(uint32_t*)(dst0 + D + ng * 8) = lx;
        *(uint32_t*)(dst1 + ng * 8)     = hy;
        *(uint32_t*)(dst1 + D + ng * 8) = ly;
    }
}

// ---------------------------------------------------------------------------
// launch
// ---------------------------------------------------------------------------
extern "C" void kernel_launch(void* const* d_in, const int* in_sizes, int n_in,
                              void* d_out, int out_size)
{
    const float* query = (const float*)d_in[0];
    const float* key_  = (const float*)d_in[1];
    const float* value = (const float*)d_in[2];
    const int*   amask = (const int*)  d_in[3];
    const float* w_q = (const float*)d_in[4];
    const float* b_q = (const float*)d_in[5];
    const float* w_k = (const float*)d_in[6];
    const float* b_k = (const float*)d_in[7];
    const float* w_v = (const float*)d_in[8];
    const float* b_v = (const float*)d_in[9];
    const float* w_o = (const float*)d_in[10];
    const float* b_o = (const float*)d_in[11];
    float* out = (float*)d_out;

    __nv_bfloat16 *gab3, *gwb4, *gqkvb;
    cudaGetSymbolAddress((void**)&gab3,  g_ab3);
    cudaGetSymbolAddress((void**)&gwb4,  g_wb4);
    cudaGetSymbolAddress((void**)&gqkvb, g_qkvb);

    cudaFuncSetAttribute(gemm_tc, cudaFuncAttributeMaxDynamicSharedMemorySize, GEMM_SMEM);
    cudaFuncSetAttribute(attn_mma, cudaFuncAttributeMaxDynamicSharedMemorySize, ATT_SMEM);

    conv_acts<<<dim3(M_TOTAL * D / (4 * 256), 3), 256>>>(query, key_, value, gab3);
    conv_ws  <<<dim3(D * D / (4 * 256), 4), 256>>>(w_q, w_k, w_v, w_o, gwb4);

    gemm_tc<<<dim3(D / 128, M_TOTAL / 128, 3), 512, GEMM_SMEM>>>(
        gab3, gwb4, b_q, b_k, b_v, nullptr, gqkvb, 1);

    attn_mma<<<dim3(S / ATQ, H, B), 256, ATT_SMEM>>>(gqkvb, amask, gab3);

    gemm_tc<<<dim3(D / 128, M_TOTAL / 128, 1), 512, GEMM_SMEM>>>(
        gab3, gwb4 + 3 * W_SLOT, b_o, b_o, b_o, out, nullptr, 0);
}